// round 6
// baseline (speedup 1.0000x reference)
#include <cuda_runtime.h>
#include <cuda_bf16.h>
#include <cstdint>

// Problem constants (fixed by the dataset)
#define Bsz 8
#define Nn  512
#define Dd  256
#define Ee  16384

// Scratch: AB_bf[b*N + n][0:256] = F@W1_top + b1, [256:512] = F@W1_bot  (4 MB)
__device__ __nv_bfloat16 g_AB[(size_t)Bsz * Nn * 512];

// ---------------------------------------------------------------------------
// tf32 helpers (mma.sync is baseline PTX — compiles for sm_103 without 'a')
// ---------------------------------------------------------------------------
__device__ __forceinline__ uint32_t f2tf32(float x) {
    uint32_t r;
    asm("cvt.rna.tf32.f32 %0, %1;" : "=r"(r) : "f"(x));
    return r;
}

__device__ __forceinline__ void mma_tf32(
    float c[4], uint32_t a0, uint32_t a1, uint32_t a2, uint32_t a3,
    uint32_t b0, uint32_t b1)
{
    asm volatile(
        "mma.sync.aligned.m16n8k8.row.col.f32.tf32.tf32.f32 "
        "{%0,%1,%2,%3}, {%4,%5,%6,%7}, {%8,%9}, {%0,%1,%2,%3};"
        : "+f"(c[0]), "+f"(c[1]), "+f"(c[2]), "+f"(c[3])
        : "r"(a0), "r"(a1), "r"(a2), "r"(a3), "r"(b0), "r"(b1));
}

// ---------------------------------------------------------------------------
// Phase 1: tensor GEMM  AB(4096 x 512) = F(4096 x 256) @ Wc(256 x 512)
//   Wc[k][j] = W1[k*256 + j]             (j < 256)
//            = W1[(256+k)*256 + (j-256)] (j >= 256)
// CTA tile M=128 x N=64, K chunked by 32 through smem. 8 warps, 32x32 each.
// Epilogue: add b1 to cols < 256, round to bf16, store to g_AB.
// ---------------------------------------------------------------------------
#define A_STRIDE 36   /* 32 + 4 pad: conflict-free fragment LDS */
#define B_STRIDE 72   /* 64 + 8 pad */

__global__ __launch_bounds__(256) void gemm_tc_kernel(
    const float* __restrict__ F, const float* __restrict__ W1,
    const float* __restrict__ b1v, __nv_bfloat16* __restrict__ AB)
{
    __shared__ uint32_t As[128 * A_STRIDE];   // 18432 B
    __shared__ uint32_t Bs[32 * B_STRIDE];    //  9216 B

    const int tid  = threadIdx.x;
    const int wid  = tid >> 5;
    const int lane = tid & 31;
    const int lq   = lane >> 2;   // 0..7
    const int lr   = lane & 3;    // 0..3

    const int n0 = blockIdx.x * 64;    // 0..448
    const int m0 = blockIdx.y * 128;   // 0..3968

    const int wm = wid >> 1;          // 0..3  (m quadrant, 32 rows)
    const int wn = wid & 1;           // 0..1  (n half, 32 cols)

    const float* Wsrc = (n0 < 256) ? (W1 + n0) : (W1 + 256 * 256 + (n0 - 256));

    float c[2][4][4] = {};            // [m-tile][n-tile][frag]

    for (int kc = 0; kc < 256; kc += 32) {
        // ---- Load A chunk: 128 rows x 32 k, coalesced float4, cvt to tf32
#pragma unroll
        for (int it = 0; it < 4; it++) {
            const int idx = it * 256 + tid;       // [0,1024)
            const int row = idx >> 3;
            const int k4  = idx & 7;
            float4 v = *(const float4*)(F + (size_t)(m0 + row) * 256 + kc + k4 * 4);
            uint32_t* d = &As[row * A_STRIDE + k4 * 4];
            d[0] = f2tf32(v.x); d[1] = f2tf32(v.y);
            d[2] = f2tf32(v.z); d[3] = f2tf32(v.w);
        }
        // ---- Load B chunk: 32 k x 64 n
#pragma unroll
        for (int it = 0; it < 2; it++) {
            const int idx = it * 256 + tid;       // [0,512)
            const int k   = idx >> 4;
            const int n4  = idx & 15;
            float4 v = *(const float4*)(Wsrc + (size_t)(kc + k) * 256 + n4 * 4);
            uint32_t* d = &Bs[k * B_STRIDE + n4 * 4];
            d[0] = f2tf32(v.x); d[1] = f2tf32(v.y);
            d[2] = f2tf32(v.z); d[3] = f2tf32(v.w);
        }
        __syncthreads();

        // ---- Compute: 4 k-steps of 8
#pragma unroll
        for (int k0 = 0; k0 < 32; k0 += 8) {
            uint32_t a[2][4];
#pragma unroll
            for (int i = 0; i < 2; i++) {
                const int rb = (wm * 32 + i * 16 + lq) * A_STRIDE + k0 + lr;
                a[i][0] = As[rb];
                a[i][1] = As[rb + 8 * A_STRIDE];
                a[i][2] = As[rb + 4];
                a[i][3] = As[rb + 8 * A_STRIDE + 4];
            }
            uint32_t b[4][2];
#pragma unroll
            for (int j = 0; j < 4; j++) {
                const int cb = (k0 + lr) * B_STRIDE + wn * 32 + j * 8 + lq;
                b[j][0] = Bs[cb];
                b[j][1] = Bs[cb + 4 * B_STRIDE];
            }
#pragma unroll
            for (int i = 0; i < 2; i++)
#pragma unroll
                for (int j = 0; j < 4; j++)
                    mma_tf32(c[i][j], a[i][0], a[i][1], a[i][2], a[i][3],
                             b[j][0], b[j][1]);
        }
        __syncthreads();
    }

    // ---- Epilogue: add b1 (cols<256 only), pack to bf16, store.
    // Fragment layout: c[.][j][0..1] -> row lq, cols 2lr,2lr+1; [2..3] -> row lq+8.
    float2 bias[4];
#pragma unroll
    for (int j = 0; j < 4; j++) {
        const int col = n0 + wn * 32 + j * 8 + 2 * lr;
        bias[j] = (n0 < 256) ? *(const float2*)(b1v + col)
                             : make_float2(0.f, 0.f);
    }
#pragma unroll
    for (int i = 0; i < 2; i++) {
        const int rbase = m0 + wm * 32 + i * 16 + lq;
#pragma unroll
        for (int j = 0; j < 4; j++) {
            const int col = n0 + wn * 32 + j * 8 + 2 * lr;
            float2 v0 = make_float2(c[i][j][0] + bias[j].x, c[i][j][1] + bias[j].y);
            float2 v1 = make_float2(c[i][j][2] + bias[j].x, c[i][j][3] + bias[j].y);
            *(__nv_bfloat162*)(AB + (size_t)rbase * 512 + col) =
                __float22bfloat162_rn(v0);
            *(__nv_bfloat162*)(AB + (size_t)(rbase + 8) * 512 + col) =
                __float22bfloat162_rn(v1);
        }
    }
}

// ---------------------------------------------------------------------------
// Phase 2: per-(b,e) edge MLP tail + scatter.  AB is bf16, b1 pre-folded.
// One warp per (b,e), 4 pairs per warp with all 8 gathers issued up front.
// ---------------------------------------------------------------------------
__global__ __launch_bounds__(256) void edge_kernel(
    const __nv_bfloat16* __restrict__ AB,
    const float* __restrict__ W2,
    const float* __restrict__ b2,
    const void* __restrict__ edge_raw,
    float* __restrict__ out)
{
    const int tid  = threadIdx.x;
    const int warp = tid >> 5;
    const int lane = tid & 31;
    const int ch   = lane * 8;          // 8 channels per lane

    const int*       e32 = (const int*)edge_raw;
    const long long* e64 = (const long long*)edge_raw;

    // In-warp dtype detection: int64 buffer has all odd words zero.
    int vdet = e32[2 * lane + 1];
    unsigned any = __ballot_sync(0xffffffffu, vdet != 0);
    const bool is64 = (any == 0u);

    const float4 w2a = *(const float4*)(W2 + ch);
    const float4 w2b = *(const float4*)(W2 + ch + 4);
    const float  b2v = b2[0];

    const int wslot = blockIdx.x * 8 + warp;  // 0..32767

    int srcs[4], dsts[4], bs[4];
#pragma unroll
    for (int r = 0; r < 4; r++) {
        const int g = wslot * 4 + r;            // 0..131071  (b,e) pair
        bs[r] = g >> 14;                        // E = 16384
        const int e = g & (Ee - 1);
        if (is64) {
            srcs[r] = (int)e64[e];
            dsts[r] = (int)e64[Ee + e];
        } else {
            srcs[r] = e32[e];
            dsts[r] = e32[Ee + e];
        }
    }

    // Issue all 8 row-gathers (MLP=8)
    uint4 av[4], bv[4];
#pragma unroll
    for (int r = 0; r < 4; r++) {
        const __nv_bfloat16* ar = AB + (((size_t)bs[r] * Nn + srcs[r]) << 9);
        const __nv_bfloat16* br = AB + (((size_t)bs[r] * Nn + dsts[r]) << 9) + 256;
        av[r] = *(const uint4*)(ar + ch);
        bv[r] = *(const uint4*)(br + ch);
    }

#pragma unroll
    for (int r = 0; r < 4; r++) {
        const uint32_t* ap = (const uint32_t*)&av[r];
        const uint32_t* bp = (const uint32_t*)&bv[r];

        float acc = 0.f;
#pragma unroll
        for (int p = 0; p < 4; p++) {
            float2 a2 = __bfloat1622float2(*(const __nv_bfloat162*)&ap[p]);
            float2 b2f = __bfloat1622float2(*(const __nv_bfloat162*)&bp[p]);
            const float w0 = (p < 2) ? ((p == 0) ? w2a.x : w2a.z)
                                     : ((p == 2) ? w2b.x : w2b.z);
            const float w1 = (p < 2) ? ((p == 0) ? w2a.y : w2a.w)
                                     : ((p == 2) ? w2b.y : w2b.w);
            acc += fmaxf(a2.x + b2f.x, 0.f) * w0;
            acc += fmaxf(a2.y + b2f.y, 0.f) * w1;
        }

        acc += __shfl_xor_sync(0xffffffffu, acc, 16);
        acc += __shfl_xor_sync(0xffffffffu, acc, 8);
        acc += __shfl_xor_sync(0xffffffffu, acc, 4);
        acc += __shfl_xor_sync(0xffffffffu, acc, 2);
        acc += __shfl_xor_sync(0xffffffffu, acc, 1);

        if (lane == 0) {
            const float z = acc + b2v;
            const float s = 1.0f / (1.0f + expf(-z));
            out[((size_t)bs[r] << 18) + ((size_t)srcs[r] << 9) + (size_t)dsts[r]] = s;
        }
    }
}

// ---------------------------------------------------------------------------
extern "C" void kernel_launch(void* const* d_in, const int* in_sizes, int n_in,
                              void* d_out, int out_size)
{
    const float* features = (const float*)d_in[0];   // (8,512,256)
    const float* W1       = (const float*)d_in[1];   // (512,256)
    const float* b1       = (const float*)d_in[2];   // (256)
    const float* W2       = (const float*)d_in[3];   // (256,1)
    const float* b2       = (const float*)d_in[4];   // (1)
    const void*  edge     = d_in[5];                 // (2,16384) int32 or int64
    float*       out      = (float*)d_out;           // (8,512,512)

    __nv_bfloat16* AB;
    cudaGetSymbolAddress((void**)&AB, g_AB);

    // Zero output (scatter only writes edge slots)
    cudaMemsetAsync(d_out, 0, (size_t)out_size * sizeof(float));

    // Phase 1: AB = F @ Wc  (mma.sync tf32), bf16 output with b1 folded in
    dim3 ggrid(8, 32);   // N-tiles x M-tiles
    gemm_tc_kernel<<<ggrid, 256>>>(features, W1, b1, AB);

    // Phase 2: edge MLP tail + scatter
    edge_kernel<<<4096, 256>>>(AB, W2, b2, edge, out);
}

// round 7
// speedup vs baseline: 1.3538x; 1.3538x over previous
#include <cuda_runtime.h>
#include <cuda_bf16.h>
#include <cstdint>

// Problem constants (fixed by the dataset)
#define Bsz 8
#define Nn  512
#define Dd  256
#define Ee  16384

// Scratch: AB_bf[b*N + n][0:256] = F@W1_top + b1, [256:512] = F@W1_bot  (4 MB)
__device__ __nv_bfloat16 g_AB[(size_t)Bsz * Nn * 512];

// ---------------------------------------------------------------------------
// tf32 helpers (mma.sync is baseline PTX — compiles for sm_103 without 'a')
// ---------------------------------------------------------------------------
__device__ __forceinline__ uint32_t f2tf32(float x) {
    uint32_t r;
    asm("cvt.rna.tf32.f32 %0, %1;" : "=r"(r) : "f"(x));
    return r;
}

__device__ __forceinline__ void mma_tf32(
    float c[4], uint32_t a0, uint32_t a1, uint32_t a2, uint32_t a3,
    uint32_t b0, uint32_t b1)
{
    asm volatile(
        "mma.sync.aligned.m16n8k8.row.col.f32.tf32.tf32.f32 "
        "{%0,%1,%2,%3}, {%4,%5,%6,%7}, {%8,%9}, {%0,%1,%2,%3};"
        : "+f"(c[0]), "+f"(c[1]), "+f"(c[2]), "+f"(c[3])
        : "r"(a0), "r"(a1), "r"(a2), "r"(a3), "r"(b0), "r"(b1));
}

// ---------------------------------------------------------------------------
// Phase 1: tensor GEMM  AB(4096 x 512) = F(4096 x 256) @ Wc(256 x 512)
// CTA tile M=128 x N=64, K chunked by 32, register double-buffered loads.
// Epilogue: +b1 (cols<256), round to bf16. Prologue: zero a slice of `out`.
// ---------------------------------------------------------------------------
#define A_STRIDE 36   /* 32 + 4 pad: conflict-free fragment LDS */
#define B_STRIDE 72   /* 64 + 8 pad */

__global__ __launch_bounds__(256) void gemm_tc_kernel(
    const float* __restrict__ F, const float* __restrict__ W1,
    const float* __restrict__ b1v, __nv_bfloat16* __restrict__ AB,
    float* __restrict__ outz)
{
    __shared__ uint32_t As[128 * A_STRIDE];   // 18432 B
    __shared__ uint32_t Bs[32 * B_STRIDE];    //  9216 B

    const int tid  = threadIdx.x;
    const int wid  = tid >> 5;
    const int lane = tid & 31;
    const int lq   = lane >> 2;   // 0..7
    const int lr   = lane & 3;    // 0..3

    const int n0 = blockIdx.x * 64;    // 0..448
    const int m0 = blockIdx.y * 128;   // 0..3968

    const int wm = wid >> 1;          // 0..3  (m quadrant, 32 rows)
    const int wn = wid & 1;           // 0..1  (n half, 32 cols)

    // ---- Zero the final output (replaces cudaMemsetAsync; overlaps loads)
    {
        const int gtid = (blockIdx.y * 8 + blockIdx.x) * 256 + tid; // 0..65535
        const float4 z = make_float4(0.f, 0.f, 0.f, 0.f);
#pragma unroll
        for (int i = 0; i < 8; i++)
            *(float4*)(outz + (((size_t)(i * 65536 + gtid)) << 2)) = z;
    }

    const float* Wsrc = (n0 < 256) ? (W1 + n0) : (W1 + 256 * 256 + (n0 - 256));

    // ---- Prologue: load chunk kc=0 into registers
    float4 a4[4], b4[2];
#pragma unroll
    for (int it = 0; it < 4; it++) {
        const int idx = it * 256 + tid;
        a4[it] = *(const float4*)(F + (size_t)(m0 + (idx >> 3)) * 256 + (idx & 7) * 4);
    }
#pragma unroll
    for (int it = 0; it < 2; it++) {
        const int idx = it * 256 + tid;
        b4[it] = *(const float4*)(Wsrc + (size_t)(idx >> 4) * 256 + (idx & 15) * 4);
    }

    float c[2][4][4] = {};            // [m-tile][n-tile][frag]

#pragma unroll 1
    for (int kc = 0; kc < 256; kc += 32) {
        // ---- Store current chunk regs -> smem (cvt to tf32)
#pragma unroll
        for (int it = 0; it < 4; it++) {
            const int idx = it * 256 + tid;
            uint32_t* d = &As[(idx >> 3) * A_STRIDE + (idx & 7) * 4];
            d[0] = f2tf32(a4[it].x); d[1] = f2tf32(a4[it].y);
            d[2] = f2tf32(a4[it].z); d[3] = f2tf32(a4[it].w);
        }
#pragma unroll
        for (int it = 0; it < 2; it++) {
            const int idx = it * 256 + tid;
            uint32_t* d = &Bs[(idx >> 4) * B_STRIDE + (idx & 15) * 4];
            d[0] = f2tf32(b4[it].x); d[1] = f2tf32(b4[it].y);
            d[2] = f2tf32(b4[it].z); d[3] = f2tf32(b4[it].w);
        }
        __syncthreads();

        // ---- Prefetch next chunk (overlaps with MMA below)
        if (kc < 224) {
            const int kn = kc + 32;
#pragma unroll
            for (int it = 0; it < 4; it++) {
                const int idx = it * 256 + tid;
                a4[it] = *(const float4*)(F + (size_t)(m0 + (idx >> 3)) * 256 + kn + (idx & 7) * 4);
            }
#pragma unroll
            for (int it = 0; it < 2; it++) {
                const int idx = it * 256 + tid;
                b4[it] = *(const float4*)(Wsrc + (size_t)(kn + (idx >> 4)) * 256 + (idx & 15) * 4);
            }
        }

        // ---- Compute: 4 k-steps of 8
#pragma unroll
        for (int k0 = 0; k0 < 32; k0 += 8) {
            uint32_t a[2][4];
#pragma unroll
            for (int i = 0; i < 2; i++) {
                const int rb = (wm * 32 + i * 16 + lq) * A_STRIDE + k0 + lr;
                a[i][0] = As[rb];
                a[i][1] = As[rb + 8 * A_STRIDE];
                a[i][2] = As[rb + 4];
                a[i][3] = As[rb + 8 * A_STRIDE + 4];
            }
            uint32_t b[4][2];
#pragma unroll
            for (int j = 0; j < 4; j++) {
                const int cb = (k0 + lr) * B_STRIDE + wn * 32 + j * 8 + lq;
                b[j][0] = Bs[cb];
                b[j][1] = Bs[cb + 4 * B_STRIDE];
            }
#pragma unroll
            for (int i = 0; i < 2; i++)
#pragma unroll
                for (int j = 0; j < 4; j++)
                    mma_tf32(c[i][j], a[i][0], a[i][1], a[i][2], a[i][3],
                             b[j][0], b[j][1]);
        }
        __syncthreads();
    }

    // ---- Epilogue: add b1 (cols<256 only), pack to bf16, store.
    float2 bias[4];
#pragma unroll
    for (int j = 0; j < 4; j++) {
        const int col = n0 + wn * 32 + j * 8 + 2 * lr;
        bias[j] = (n0 < 256) ? *(const float2*)(b1v + col)
                             : make_float2(0.f, 0.f);
    }
#pragma unroll
    for (int i = 0; i < 2; i++) {
        const int rbase = m0 + wm * 32 + i * 16 + lq;
#pragma unroll
        for (int j = 0; j < 4; j++) {
            const int col = n0 + wn * 32 + j * 8 + 2 * lr;
            float2 v0 = make_float2(c[i][j][0] + bias[j].x, c[i][j][1] + bias[j].y);
            float2 v1 = make_float2(c[i][j][2] + bias[j].x, c[i][j][3] + bias[j].y);
            *(__nv_bfloat162*)(AB + (size_t)rbase * 512 + col) =
                __float22bfloat162_rn(v0);
            *(__nv_bfloat162*)(AB + (size_t)(rbase + 8) * 512 + col) =
                __float22bfloat162_rn(v1);
        }
    }
}

// ---------------------------------------------------------------------------
// Phase 2: per-(b,e) edge MLP tail + scatter.  AB is bf16, b1 pre-folded.
// One warp per 4 edges. bf16x2 add/relu, fp32 dot. 6-shfl multi-edge reduce,
// sigmoid + store in parallel lane groups.
// ---------------------------------------------------------------------------
__global__ __launch_bounds__(256) void edge_kernel(
    const __nv_bfloat16* __restrict__ AB,
    const float* __restrict__ W2,
    const float* __restrict__ b2,
    const void* __restrict__ edge_raw,
    float* __restrict__ out)
{
    const int tid  = threadIdx.x;
    const int warp = tid >> 5;
    const int lane = tid & 31;
    const int ch   = lane * 8;          // 8 channels per lane

    const int*       e32 = (const int*)edge_raw;
    const long long* e64 = (const long long*)edge_raw;

    // In-warp dtype detection: int64 buffer has all odd words zero.
    int vdet = e32[2 * lane + 1];
    unsigned any = __ballot_sync(0xffffffffu, vdet != 0);
    const bool is64 = (any == 0u);

    float w[8];
    *(float4*)&w[0] = *(const float4*)(W2 + ch);
    *(float4*)&w[4] = *(const float4*)(W2 + ch + 4);
    const float b2v = b2[0];

    const int wslot = blockIdx.x * 8 + warp;  // 0..32767

    uint32_t key[4], aoff[4], boff[4];
#pragma unroll
    for (int r = 0; r < 4; r++) {
        const int g = wslot * 4 + r;            // 0..131071  (b,e) pair
        const int b = g >> 14;                  // E = 16384
        const int e = g & (Ee - 1);
        int src, dst;
        if (is64) {
            src = (int)e64[e];
            dst = (int)e64[Ee + e];
        } else {
            src = e32[e];
            dst = e32[Ee + e];
        }
        key[r]  = ((uint32_t)b << 18) | ((uint32_t)src << 9) | (uint32_t)dst;
        aoff[r] = (((uint32_t)(b * Nn + src)) << 9) + ch;
        boff[r] = (((uint32_t)(b * Nn + dst)) << 9) + 256 + ch;
    }

    // Issue all 8 row-gathers up front (MLP=8)
    uint4 av[4], bv[4];
#pragma unroll
    for (int r = 0; r < 4; r++) {
        av[r] = *(const uint4*)(AB + aoff[r]);
        bv[r] = *(const uint4*)(AB + boff[r]);
    }

    const __nv_bfloat162 z2 = __float2bfloat162_rn(0.f);
    float acc[4];
#pragma unroll
    for (int r = 0; r < 4; r++) {
        const __nv_bfloat162* ap = (const __nv_bfloat162*)&av[r];
        const __nv_bfloat162* bp = (const __nv_bfloat162*)&bv[r];
        float a = 0.f;
#pragma unroll
        for (int p = 0; p < 4; p++) {
            __nv_bfloat162 h = __hmax2(__hadd2(ap[p], bp[p]), z2);
            float2 f = __bfloat1622float2(h);
            a = fmaf(f.x, w[2 * p], a);
            a = fmaf(f.y, w[2 * p + 1], a);
        }
        acc[r] = a;
    }

    // ---- Multi-edge reduction: 6 shfls reduce all 4 edges.
    // After stage 2, lane group g = lane>>3 holds edge g's partial;
    // stages 3-5 finish within each 8-lane group.
    const bool hi16 = (lane & 16) != 0;
    float send, recv, sA, sB, t;

    send = hi16 ? acc[0] : acc[2];
    recv = __shfl_xor_sync(0xffffffffu, send, 16);
    sA   = (hi16 ? acc[2] : acc[0]) + recv;   // lanes<16: e0, lanes>=16: e2

    send = hi16 ? acc[1] : acc[3];
    recv = __shfl_xor_sync(0xffffffffu, send, 16);
    sB   = (hi16 ? acc[3] : acc[1]) + recv;   // lanes<16: e1, lanes>=16: e3

    const bool hi8 = (lane & 8) != 0;
    send = hi8 ? sA : sB;
    recv = __shfl_xor_sync(0xffffffffu, send, 8);
    t    = (hi8 ? sB : sA) + recv;            // group g holds edge g

    t += __shfl_xor_sync(0xffffffffu, t, 4);
    t += __shfl_xor_sync(0xffffffffu, t, 2);
    t += __shfl_xor_sync(0xffffffffu, t, 1);

    const int g = lane >> 3;
    const uint32_t k = (g & 2) ? ((g & 1) ? key[3] : key[2])
                               : ((g & 1) ? key[1] : key[0]);
    const float s = 1.0f / (1.0f + expf(-(t + b2v)));
    if ((lane & 7) == 0)
        out[k] = s;
}

// ---------------------------------------------------------------------------
extern "C" void kernel_launch(void* const* d_in, const int* in_sizes, int n_in,
                              void* d_out, int out_size)
{
    const float* features = (const float*)d_in[0];   // (8,512,256)
    const float* W1       = (const float*)d_in[1];   // (512,256)
    const float* b1       = (const float*)d_in[2];   // (256)
    const float* W2       = (const float*)d_in[3];   // (256,1)
    const float* b2       = (const float*)d_in[4];   // (1)
    const void*  edge     = d_in[5];                 // (2,16384) int32 or int64
    float*       out      = (float*)d_out;           // (8,512,512)

    __nv_bfloat16* AB;
    cudaGetSymbolAddress((void**)&AB, g_AB);

    // Phase 1: AB = F @ Wc (mma.sync tf32) + fold b1 + zero `out` in prologue
    dim3 ggrid(8, 32);   // N-tiles x M-tiles
    gemm_tc_kernel<<<ggrid, 256>>>(features, W1, b1, AB, out);

    // Phase 2: edge MLP tail + scatter
    edge_kernel<<<4096, 256>>>(AB, W2, b2, edge, out);
}